// round 14
// baseline (speedup 1.0000x reference)
#include <cuda_runtime.h>
#include <cstdint>

#define B_   16
#define N_   128
#define M_   1024
#define DN_  512
#define DE_  256
#define WN_  128
#define WE_  128
#define P_   512

// ------------------------- scratch (device globals) -------------------------
__device__ float d_XWc  [B_*N_*256];     // [X@Wn | X@Wn2] (row-masked)
__device__ float d_nemb [B_*N_*256];     // [h | agg] per node
__device__ float d_nodeY[B_*N_*768];     // nemb @ [lrW1|scrW1|mrW1] rows 0:256
__device__ float d_Eg   [B_*M_*DE_];     // gathered edge feats * emask
__device__ float d_EgWe [B_*M_*WE_];     // Eg@We
__device__ float d_g    [B_*M_*WE_];     // relu(L@EgWe)*emask
__device__ float d_EFp  [B_*P_*DE_];     // edge_features at pairs
__device__ float d_pf   [B_*P_*256];     // [Pm | Q] per pair
__device__ float d_hidB [B_*P_*768];     // pf @ W1 rows 256:512 (no bias/relu)
__device__ int   d_ord  [B_*M_];         // CSR edge order by src
__device__ int   d_st   [B_*(N_+1)];     // CSR bucket starts

__device__ __forceinline__ uint32_t f2tf32(float x) {
    uint32_t r;
    asm("cvt.rna.tf32.f32 %0, %1;" : "=r"(r) : "f"(x));
    return r;
}

// m-column permutation: rows m and m+8 adjacent -> fragment pairs are LDS.64
__device__ __forceinline__ int mperm(int m) {
    return (m & 0x70) | ((m & 7) << 1) | ((m >> 3) & 1);
}

// one pipeline stage (dynamic smem, 2 stages ping-pong)
// As[k][perm(m)]: A fragments (m, m+8) adjacent.
// Bs flat [kgroup(4)][n(128)][kpair(8)]: k-pairs (t4, t4+4) adjacent.
struct Stage {
    uint32_t As[32][136];
    uint32_t Bs[4 * 1032];
};

// ======= TF32 tensor-core GEMM tile (128x128, 8 warps), 2-stage pipeline ====
// BCAT=1: B dense [K,N].  BCAT=2: B cols = [B0|B1] each 128 wide (stride 128).
// BCAT=3: B cols = [B0|B1|B2] each 256 wide (stride 256).
// C tile (bx,by) of C = A @ B (+relu, row-mask). K%32==0.
template<int BCAT>
__device__ __forceinline__
void gemm_tile(Stage* st, const float* __restrict__ A,
               const float* __restrict__ B0, const float* __restrict__ B1,
               const float* __restrict__ B2,
               float* __restrict__ C, int K, int N, int ldc, int relu,
               const int* __restrict__ rowcnt, int rpb,
               int bx, int by)
{
    const int tid  = threadIdx.x;
    const int m0 = by * 128, n0 = bx * 128;
    const int lane = tid & 31, warp = tid >> 5;
    const int wm = (warp & 1) * 64, wn = (warp >> 1) * 32;
    const int g  = lane >> 2, t4 = lane & 3;

    const int am = tid >> 1;          // A loader: m row 0..127
    const int ak = (tid & 1) * 4;     //           k quad within 8
    const int pm = mperm(am);         // permuted store column
    const int bk = tid >> 5;          // B loader: k row 0..7 (within 8-group)
    const int bn = (tid & 31) * 4;    //           n quad
    const int bkp = (bk & 3) * 2 + (bk >> 2);   // k-pair slot

    const float* Aptr = A + (size_t)(m0 + am) * K + ak;
    const float* Bsrc; int bstride, bcol;
    {
        int colq = n0 + bn;
        if (BCAT == 1)      { Bsrc = B0; bstride = N; bcol = colq; }
        else if (BCAT == 2) {
            Bsrc = (colq < 128) ? B0 : B1; bstride = 128; bcol = colq & 127;
        } else {
            int th = colq >> 8;
            Bsrc = th == 0 ? B0 : (th == 1 ? B1 : B2);
            bstride = 256; bcol = colq & 255;
        }
    }

    float acc[4][4][4];
#pragma unroll
    for (int a = 0; a < 4; a++)
#pragma unroll
        for (int b = 0; b < 4; b++)
#pragma unroll
            for (int c = 0; c < 4; c++) acc[a][b][c] = 0.0f;

    float4 pa[4], pb[4];
    // prologue: chunk 0 -> stage 0, prefetch chunk 1 into regs
#pragma unroll
    for (int ks = 0; ks < 4; ks++) {
        pa[ks] = *(const float4*)(Aptr + ks * 8);
        pb[ks] = *(const float4*)(Bsrc + (size_t)(ks * 8 + bk) * bstride + bcol);
    }
#pragma unroll
    for (int ks = 0; ks < 4; ks++) {
        st[0].As[ks * 8 + ak + 0][pm] = f2tf32(pa[ks].x);
        st[0].As[ks * 8 + ak + 1][pm] = f2tf32(pa[ks].y);
        st[0].As[ks * 8 + ak + 2][pm] = f2tf32(pa[ks].z);
        st[0].As[ks * 8 + ak + 3][pm] = f2tf32(pa[ks].w);
        uint32_t* p = &st[0].Bs[ks * 1032 + bn * 8 + bkp];
        p[0]  = f2tf32(pb[ks].x); p[8]  = f2tf32(pb[ks].y);
        p[16] = f2tf32(pb[ks].z); p[24] = f2tf32(pb[ks].w);
    }
    if (32 < K) {
#pragma unroll
        for (int ks = 0; ks < 4; ks++) {
            pa[ks] = *(const float4*)(Aptr + 32 + ks * 8);
            pb[ks] = *(const float4*)(Bsrc + (size_t)(32 + ks * 8 + bk) * bstride + bcol);
        }
    }
    __syncthreads();

    int s = 0;
    for (int k0 = 0; k0 < K; k0 += 32, s ^= 1) {
        if (k0 + 32 < K) {
            Stage& nx = st[s ^ 1];
#pragma unroll
            for (int ks = 0; ks < 4; ks++) {
                nx.As[ks * 8 + ak + 0][pm] = f2tf32(pa[ks].x);
                nx.As[ks * 8 + ak + 1][pm] = f2tf32(pa[ks].y);
                nx.As[ks * 8 + ak + 2][pm] = f2tf32(pa[ks].z);
                nx.As[ks * 8 + ak + 3][pm] = f2tf32(pa[ks].w);
                uint32_t* p = &nx.Bs[ks * 1032 + bn * 8 + bkp];
                p[0]  = f2tf32(pb[ks].x); p[8]  = f2tf32(pb[ks].y);
                p[16] = f2tf32(pb[ks].z); p[24] = f2tf32(pb[ks].w);
            }
            if (k0 + 64 < K) {
#pragma unroll
                for (int ks = 0; ks < 4; ks++) {
                    pa[ks] = *(const float4*)(Aptr + k0 + 64 + ks * 8);
                    pb[ks] = *(const float4*)(Bsrc + (size_t)(k0 + 64 + ks * 8 + bk) * bstride + bcol);
                }
            }
        }
        Stage& cu = st[s];
#pragma unroll
        for (int kk = 0; kk < 32; kk += 8) {
            uint32_t aF[4][4], bF[4][2];
            const int kg = kk >> 3;
#pragma unroll
            for (int mt = 0; mt < 4; mt++) {
                int col = wm + mt * 16 + 2 * g;
                uint2 a01 = *(const uint2*)&cu.As[kk + t4    ][col];
                uint2 a23 = *(const uint2*)&cu.As[kk + t4 + 4][col];
                aF[mt][0] = a01.x; aF[mt][1] = a01.y;
                aF[mt][2] = a23.x; aF[mt][3] = a23.y;
            }
#pragma unroll
            for (int nt = 0; nt < 4; nt++) {
                int nb = wn + nt * 8 + g;
                uint2 b01 = *(const uint2*)&cu.Bs[kg * 1032 + nb * 8 + t4 * 2];
                bF[nt][0] = b01.x; bF[nt][1] = b01.y;
            }
#pragma unroll
            for (int mt = 0; mt < 4; mt++)
#pragma unroll
                for (int nt = 0; nt < 4; nt++)
                    asm volatile(
                        "mma.sync.aligned.m16n8k8.row.col.f32.tf32.tf32.f32 "
                        "{%0,%1,%2,%3}, {%4,%5,%6,%7}, {%8,%9}, {%0,%1,%2,%3};"
                        : "+f"(acc[mt][nt][0]), "+f"(acc[mt][nt][1]),
                          "+f"(acc[mt][nt][2]), "+f"(acc[mt][nt][3])
                        : "r"(aF[mt][0]), "r"(aF[mt][1]), "r"(aF[mt][2]), "r"(aF[mt][3]),
                          "r"(bF[nt][0]), "r"(bF[nt][1]));
        }
        __syncthreads();
    }

#pragma unroll
    for (int mt = 0; mt < 4; mt++) {
        int row0 = m0 + wm + mt * 16 + g;
        int row1 = row0 + 8;
        float mask0 = 1.0f, mask1 = 1.0f;
        if (rowcnt) {
            if (row0 % rpb >= rowcnt[row0 / rpb]) mask0 = 0.0f;
            if (row1 % rpb >= rowcnt[row1 / rpb]) mask1 = 0.0f;
        }
        float* c0p = C + (size_t)row0 * ldc;
        float* c1p = C + (size_t)row1 * ldc;
#pragma unroll
        for (int nt = 0; nt < 4; nt++) {
            int col = n0 + wn + nt * 8 + 2 * t4;
            float v0 = acc[mt][nt][0], v1 = acc[mt][nt][1];
            float v2 = acc[mt][nt][2], v3 = acc[mt][nt][3];
            if (relu) {
                v0 = fmaxf(v0, 0.f); v1 = fmaxf(v1, 0.f);
                v2 = fmaxf(v2, 0.f); v3 = fmaxf(v3, 0.f);
            }
            float2 w0 = make_float2(v0 * mask0, v1 * mask0);
            float2 w1 = make_float2(v2 * mask1, v3 * mask1);
            *(float2*)(c0p + col) = w0;
            *(float2*)(c1p + col) = w1;
        }
    }
}

// ---- batch A: XWc (32, K=512, cat2) | EgWe (128) | Q (64) ------------------
__global__ __launch_bounds__(256)
void gemm_batchA(const float* __restrict__ NF,
                 const float* __restrict__ Wn, const float* __restrict__ Wn2,
                 const float* __restrict__ We, const float* __restrict__ We2,
                 const int* __restrict__ NOBJ)
{
    extern __shared__ Stage st[];
    int bid = blockIdx.x;
    if (bid < 32) {
        gemm_tile<2>(st, NF, Wn, Wn2, nullptr, d_XWc, DN_, 256, 256, 0,
                     NOBJ, N_, bid & 1, bid >> 1);
    } else if (bid < 160) {
        gemm_tile<1>(st, d_Eg, We, nullptr, nullptr, d_EgWe, DE_, WE_, WE_, 0,
                     nullptr, 0, 0, bid - 32);
    } else {
        gemm_tile<1>(st, d_EFp, We2, nullptr, nullptr, d_pf + 128, DE_, WE_, 256, 1,
                     nullptr, 0, 0, bid - 160);
    }
}

// ---- batch B: hidB (384, cat3 rows 256:512) | nodeY (96, cat3 rows 0:256) --
__global__ __launch_bounds__(256)
void gemm_batchB(const float* __restrict__ lrW1, const float* __restrict__ scrW1,
                 const float* __restrict__ mrW1)
{
    extern __shared__ Stage st[];
    int bid = blockIdx.x;
    if (bid < 384) {
        gemm_tile<3>(st, d_pf, lrW1 + 256 * 256, scrW1 + 256 * 256, mrW1 + 256 * 256,
                     d_hidB, 256, 768, 768, 0, nullptr, 0, bid % 6, bid / 6);
    } else {
        int t = bid - 384;
        gemm_tile<3>(st, d_nemb, lrW1, scrW1, mrW1,
                     d_nodeY, 256, 768, 768, 0, nullptr, 0, t % 6, t / 6);
    }
}

// ------- merged gathers: eg (16384 blocks) | efp (8192 blocks), 64 thr ------
__global__ void gathers(const float* __restrict__ EF, const int* __restrict__ eidx,
                        const int* __restrict__ pairs, const int* __restrict__ nedg)
{
    int bid = blockIdx.x;
    if (bid < B_ * M_) {
        int b = bid / M_, m = bid % M_;
        int s = eidx[(b * 2 + 0) * M_ + m];
        int d = eidx[(b * 2 + 1) * M_ + m];
        bool on = m < nedg[b];
        const float4* src = (const float4*)(EF + (((size_t)b * N_ + s) * N_ + d) * DE_);
        float4* dst = (float4*)(d_Eg + ((size_t)b * M_ + m) * DE_);
        float4 z = make_float4(0.f, 0.f, 0.f, 0.f);
        for (int t = threadIdx.x; t < DE_ / 4; t += blockDim.x)
            dst[t] = on ? src[t] : z;
    } else {
        int t2 = bid - B_ * M_;
        int b = t2 / P_, p = t2 % P_;
        int p0 = pairs[((size_t)b * P_ + p) * 2 + 0];
        int p1 = pairs[((size_t)b * P_ + p) * 2 + 1];
        const float4* src = (const float4*)(EF + (((size_t)b * N_ + p0) * N_ + p1) * DE_);
        float4* dst = (float4*)(d_EFp + ((size_t)b * P_ + p) * DE_);
        for (int t = threadIdx.x; t < DE_ / 4; t += blockDim.x)
            dst[t] = src[t];
    }
}

// ------ stage 3 merged: g (16384 first) | h (2048) | pm (8192), 128 thr -----
__global__ __launch_bounds__(128)
void stage3(const float* __restrict__ ADJ, const float* __restrict__ LADJ,
            const int* __restrict__ PAIRS, const int* __restrict__ NOBJ,
            const int* __restrict__ NEDG)
{
    __shared__ float s_val[M_];
    __shared__ int   s_idx[M_];
    __shared__ float s_red[4][128];
    __shared__ int   wsum[4];
    int bid = blockIdx.x;
    int w = threadIdx.x;                    // 128
    int lane = w & 31, wp = w >> 5;

    if (bid < B_ * M_) {
        int b = bid / M_, m = bid % M_;
        const float* Lrow = LADJ + ((size_t)b * M_ + m) * M_;
        float4 va = ((const float4*)Lrow)[w * 2];
        float4 vb = ((const float4*)Lrow)[w * 2 + 1];
        float v[8] = {va.x, va.y, va.z, va.w, vb.x, vb.y, vb.z, vb.w};
        int cnt = 0;
#pragma unroll
        for (int t = 0; t < 8; t++)
            if (v[t] != 0.0f) cnt++;
        int inc = cnt;
#pragma unroll
        for (int d = 1; d < 32; d <<= 1) {
            int t = __shfl_up_sync(0xffffffffu, inc, d);
            if (lane >= d) inc += t;
        }
        if (lane == 31) wsum[wp] = inc;
        __syncthreads();
        int woff = 0;
#pragma unroll
        for (int ww = 0; ww < 4; ww++)
            if (ww < wp) woff += wsum[ww];
        int pos = woff + inc - cnt;
        int base = w * 8;
#pragma unroll
        for (int t = 0; t < 8; t++)
            if (v[t] != 0.0f) { s_idx[pos] = base + t; s_val[pos] = v[t]; pos++; }
        int total = wsum[0] + wsum[1] + wsum[2] + wsum[3];
        __syncthreads();

        const float* Eb = d_EgWe + (size_t)b * M_ * WE_;
        float4 a0 = make_float4(0.f, 0.f, 0.f, 0.f), a1 = a0;
        if (wp == 0)
            a0 = ((const float4*)(Eb + (size_t)m * WE_))[lane];
        int p = wp;
        for (; p + 4 < total; p += 8) {
            float sv0 = s_val[p];     const float4 e0 = ((const float4*)(Eb + (size_t)s_idx[p]     * WE_))[lane];
            float sv1 = s_val[p + 4]; const float4 e1 = ((const float4*)(Eb + (size_t)s_idx[p + 4] * WE_))[lane];
            a0.x += sv0 * e0.x; a0.y += sv0 * e0.y; a0.z += sv0 * e0.z; a0.w += sv0 * e0.w;
            a1.x += sv1 * e1.x; a1.y += sv1 * e1.y; a1.z += sv1 * e1.z; a1.w += sv1 * e1.w;
        }
        if (p < total) {
            float sv = s_val[p]; const float4 e = ((const float4*)(Eb + (size_t)s_idx[p] * WE_))[lane];
            a0.x += sv * e.x; a0.y += sv * e.y; a0.z += sv * e.z; a0.w += sv * e.w;
        }
        a0.x += a1.x; a0.y += a1.y; a0.z += a1.z; a0.w += a1.w;
        ((float4*)&s_red[wp][0])[lane] = a0;
        __syncthreads();
        float acc = s_red[0][w] + s_red[1][w] + s_red[2][w] + s_red[3][w];
        d_g[((size_t)b * M_ + m) * WE_ + w] =
            (m < NEDG[b]) ? fmaxf(acc, 0.0f) : 0.0f;
    } else if (bid < B_ * M_ + B_ * N_) {
        int t = bid - B_ * M_;
        int b = t / N_, i = t % N_;
        float v = ADJ[((size_t)b * N_ + i) * N_ + w];
        bool nz = v != 0.0f;
        unsigned mk = __ballot_sync(0xffffffffu, nz);
        int rank = __popc(mk & ((1u << lane) - 1));
        if (lane == 0) wsum[wp] = __popc(mk);
        __syncthreads();
        int off = 0;
#pragma unroll
        for (int ww = 0; ww < 4; ww++)
            if (ww < wp) off += wsum[ww];
        if (nz) { s_idx[off + rank] = w; s_val[off + rank] = v; }
        int total = wsum[0] + wsum[1] + wsum[2] + wsum[3];
        __syncthreads();

        const float* XWb = d_XWc + (size_t)b * N_ * 256;
        float4 a0 = make_float4(0.f, 0.f, 0.f, 0.f), a1 = a0;
        if (wp == 0)
            a0 = ((const float4*)(XWb + (size_t)i * 256))[lane];
        int p = wp;
        for (; p + 4 < total; p += 8) {
            float sv0 = s_val[p];     const float4 e0 = ((const float4*)(XWb + (size_t)s_idx[p]     * 256))[lane];
            float sv1 = s_val[p + 4]; const float4 e1 = ((const float4*)(XWb + (size_t)s_idx[p + 4] * 256))[lane];
            a0.x += sv0 * e0.x; a0.y += sv0 * e0.y; a0.z += sv0 * e0.z; a0.w += sv0 * e0.w;
            a1.x += sv1 * e1.x; a1.y += sv1 * e1.y; a1.z += sv1 * e1.z; a1.w += sv1 * e1.w;
        }
        if (p < total) {
            float sv = s_val[p]; const float4 e = ((const float4*)(XWb + (size_t)s_idx[p] * 256))[lane];
            a0.x += sv * e.x; a0.y += sv * e.y; a0.z += sv * e.z; a0.w += sv * e.w;
        }
        a0.x += a1.x; a0.y += a1.y; a0.z += a1.z; a0.w += a1.w;
        ((float4*)&s_red[wp][0])[lane] = a0;
        __syncthreads();
        float acc = s_red[0][w] + s_red[1][w] + s_red[2][w] + s_red[3][w];
        d_nemb[((size_t)b * N_ + i) * 256 + w] =
            (i < NOBJ[b]) ? fmaxf(acc, 0.0f) : 0.0f;
    } else {
        int t = bid - B_ * M_ - B_ * N_;
        int b = t / P_, p = t % P_;
        int p0 = PAIRS[((size_t)b * P_ + p) * 2 + 0];
        int p1 = PAIRS[((size_t)b * P_ + p) * 2 + 1];
        const float* xb = d_XWc + (size_t)b * N_ * 256 + 128;
        d_pf[((size_t)b * P_ + p) * 256 + w] =
            fmaxf(xb[(size_t)p0 * 256 + w] + xb[(size_t)p1 * 256 + w], 0.0f);
    }
}

// ---------------- CSR build: bucket edges by src, stable in m ---------------
__global__ __launch_bounds__(1024)
void csr_kernel(const int* __restrict__ eidx,
                int* __restrict__ order, int* __restrict__ start)
{
    int b = blockIdx.x, m = threadIdx.x;    // 1024 threads
    int warp = m >> 5, lane = m & 31;
    __shared__ int ssrc[M_];
    __shared__ int wcnt[32][N_];
    __shared__ int cnt[N_ + 1];
    ssrc[m] = eidx[(b * 2 + 0) * M_ + m];
    for (int i = m; i < 32 * N_; i += 1024) (&wcnt[0][0])[i] = 0;
    __syncthreads();
    int s = ssrc[m];
    unsigned mk = __match_any_sync(0xffffffffu, s);
    int rank_w = __popc(mk & ((1u << lane) - 1));
    if (lane == (__ffs(mk) - 1)) wcnt[warp][s] = __popc(mk);
    __syncthreads();
    int rank = rank_w;
    for (int ww = 0; ww < warp; ww++) rank += wcnt[ww][s];
    if (m < N_) {
        int t = 0;
        for (int ww = 0; ww < 32; ww++) t += wcnt[ww][m];
        cnt[m + 1] = t;
    }
    if (m == 0) cnt[0] = 0;
    __syncthreads();
    if (m == 0)
        for (int i = 1; i <= N_; i++) cnt[i] += cnt[i - 1];
    __syncthreads();
    order[b * M_ + cnt[s] + rank] = m;
    if (m < N_ + 1) start[b * (N_ + 1) + m] = cnt[m];
}

// -------- agg[b,n] = sum_{m in bucket n, ascending m} g[b,m] * nmask --------
__global__ void agg2_kernel(const int* __restrict__ nobj)
{
    int b = blockIdx.x / N_, n = blockIdx.x % N_;
    int w = threadIdx.x;                    // 128
    int s0 = d_st[b * (N_ + 1) + n], s1 = d_st[b * (N_ + 1) + n + 1];
    const float* gb = d_g + (size_t)b * M_ * WE_;
    const int* ob = d_ord + b * M_;
    float acc = 0.0f;
    for (int i = s0; i < s1; i++)
        acc += gb[(size_t)ob[i] * WE_ + w];
    d_nemb[((size_t)b * N_ + n) * 256 + 128 + w] = (n < nobj[b]) ? acc : 0.0f;
}

// ------ layer-2 heads: hid = relu(hidB + nY[p0] + nY[p1] + b1) fused --------
// W2 matrices staged in dynamic shared (coalesced once per block).
__global__ void head2_kernel(const int* __restrict__ pairs,
                             const float* __restrict__ lrb1,
                             const float* __restrict__ scrb1,
                             const float* __restrict__ mrb1,
                             const float* __restrict__ lrW2, const float* __restrict__ lrb2,
                             const float* __restrict__ crW2, const float* __restrict__ crb2,
                             const float* __restrict__ mrW2, const float* __restrict__ mrb2,
                             float* __restrict__ out)
{
    extern __shared__ float dynsh[];
    float* sh  = dynsh;                 // 8*768
    float* w2s = dynsh + 8 * 768;       // 2304 + 1536 + 4352 = 8192
    __shared__ int sp[16];
    int tid = threadIdx.x;                  // 256
    int blk = blockIdx.x;                   // 8 pairs per block
    if (tid < 16) sp[tid] = pairs[(size_t)blk * 16 + tid];
    for (int i = tid; i < 2304; i += 256) w2s[i] = lrW2[i];
    for (int i = tid; i < 1536; i += 256) w2s[2304 + i] = crW2[i];
    for (int i = tid; i < 4352; i += 256) w2s[3840 + i] = mrW2[i];
    __syncthreads();
    int b = (blk * 8) / P_;
    const float* nYb = d_nodeY + (size_t)b * N_ * 768;
    for (int i = tid; i < 8 * 768; i += 256) {
        int lp = i / 768, col = i - lp * 768;
        int gg = blk * 8 + lp;
        float b1 = (col < 256) ? lrb1[col]
                 : (col < 512) ? scrb1[col - 256] : mrb1[col - 512];
        float v = d_hidB[(size_t)gg * 768 + col]
                + nYb[(size_t)sp[lp * 2 + 0] * 768 + col]
                + nYb[(size_t)sp[lp * 2 + 1] * 768 + col] + b1;
        sh[i] = fmaxf(v, 0.0f);
    }
    __syncthreads();
    int lp = tid / 32, j = tid % 32;
    int pr = blk * 8 + lp;
    const float* W2; float bias; int nout, oj; const float* hr; size_t obase;
    if (j < 9)       { W2 = w2s;        oj = j;      bias = lrb2[oj]; nout = 9;  hr = sh + lp * 768;       obase = 0; }
    else if (j < 15) { W2 = w2s + 2304; oj = j - 9;  bias = crb2[oj]; nout = 6;  hr = sh + lp * 768 + 256; obase = (size_t)B_ * P_ * 9; }
    else             { W2 = w2s + 3840; oj = j - 15; bias = mrb2[oj]; nout = 17; hr = sh + lp * 768 + 512; obase = (size_t)B_ * P_ * 15; }
    float acc = bias;
#pragma unroll 8
    for (int k = 0; k < 256; k++)
        acc += hr[k] * W2[k * nout + oj];
    out[obase + (size_t)pr * nout + oj] = acc;
}

// ============================================================================
extern "C" void kernel_launch(void* const* d_in, const int* in_sizes, int n_in,
                              void* d_out, int out_size)
{
    const float* NF    = (const float*)d_in[0];
    const float* EF    = (const float*)d_in[1];
    const float* ADJ   = (const float*)d_in[2];
    const float* LADJ  = (const float*)d_in[3];
    const int*   EIDX  = (const int*)  d_in[4];
    const int*   PAIRS = (const int*)  d_in[5];
    const int*   NOBJ  = (const int*)  d_in[6];
    const int*   NEDG  = (const int*)  d_in[7];
    const float* Wn    = (const float*)d_in[8];
    const float* We    = (const float*)d_in[9];
    const float* Wn2   = (const float*)d_in[10];
    const float* We2   = (const float*)d_in[11];
    const float* scrW1 = (const float*)d_in[12];
    const float* scrb1 = (const float*)d_in[13];
    const float* scrW2 = (const float*)d_in[14];
    const float* scrb2 = (const float*)d_in[15];
    const float* lrW1  = (const float*)d_in[16];
    const float* lrb1  = (const float*)d_in[17];
    const float* lrW2  = (const float*)d_in[18];
    const float* lrb2  = (const float*)d_in[19];
    const float* mrW1  = (const float*)d_in[20];
    const float* mrb1  = (const float*)d_in[21];
    const float* mrW2  = (const float*)d_in[22];
    const float* mrb2  = (const float*)d_in[23];
    float* out = (float*)d_out;

    int *ord, *st;
    cudaGetSymbolAddress((void**)&ord, d_ord);
    cudaGetSymbolAddress((void**)&st,  d_st);

    const int gemmSmem  = 2 * (int)sizeof(Stage);          // 67840
    const int head2Smem = (8 * 768 + 8192) * (int)sizeof(float);   // 57344
    cudaFuncSetAttribute(gemm_batchA, cudaFuncAttributeMaxDynamicSharedMemorySize, gemmSmem);
    cudaFuncSetAttribute(gemm_batchB, cudaFuncAttributeMaxDynamicSharedMemorySize, gemmSmem);
    cudaFuncSetAttribute(head2_kernel, cudaFuncAttributeMaxDynamicSharedMemorySize, head2Smem);

    // stage 1: CSR + merged gathers (independent)
    csr_kernel<<<B_, 1024>>>(EIDX, ord, st);
    gathers<<<B_ * M_ + B_ * P_, 64>>>(EF, EIDX, PAIRS, NEDG);

    // stage 2: batched GEMM A — XWc(32,K=512,cat2) | EgWe(128) | Q(64)
    gemm_batchA<<<224, 256, gemmSmem>>>(NF, Wn, Wn2, We, We2, NOBJ);

    // stage 3: merged g | h | pm, then deterministic scatter-add
    stage3<<<B_ * M_ + B_ * N_ + B_ * P_, 128>>>(ADJ, LADJ, PAIRS, NOBJ, NEDG);
    agg2_kernel<<<B_ * N_, 128>>>(NOBJ);

    // stage 4: batched GEMM B — hidB(384,cat3) | nodeY(96,cat3)
    gemm_batchB<<<480, 256, gemmSmem>>>(lrW1, scrW1, mrW1);

    // stage 5: fused relu-sum (+b1) + layer-2 heads -> out
    head2_kernel<<<B_ * P_ / 8, 256, head2Smem>>>(PAIRS, lrb1, scrb1, mrb1,
                                                  lrW2, lrb2, scrW2, scrb2,
                                                  mrW2, mrb2, out);
}